// round 1
// baseline (speedup 1.0000x reference)
#include <cuda_runtime.h>
#include <math.h>

// Problem constants
namespace {
constexpr int B = 64, T = 256, E = 512, H = 512, TAGS = 50;
constexpr int G = 4 * H;   // 2048 (gate dim)
constexpr int M = T * B;   // 16384 rows of [time-major, batch] matrix
}

// Scratch (static device arrays — no cudaMalloc allowed)
__device__ float g_xs[M * E];        //  32 MB  embedded inputs [T*B, E]
__device__ float g_pre_f[M * G];     // 128 MB  precomputed x@Wih^T + biases (fwd)
__device__ float g_pre_b[M * G];     // 128 MB  (bwd)
__device__ float g_out1[M * 2 * H];  //  64 MB  layer-1 output [T*B, 2H]
__device__ float g_out2[M * 2 * H];  //  64 MB  layer-2 output
__device__ float g_h[2][2][B * H];   // h double buffer [parity][dir]
__device__ float g_c[2][B * H];      // c state [dir]

// ---------------------------------------------------------------------------
__global__ void zero_states_kernel() {
  int i = blockIdx.x * blockDim.x + threadIdx.x;
  if (i < B * H) {
    g_h[0][0][i] = 0.f; g_h[0][1][i] = 0.f;
    g_h[1][0][i] = 0.f; g_h[1][1][i] = 0.f;
    g_c[0][i] = 0.f;    g_c[1][i] = 0.f;
  }
}

// Embedding gather: g_xs[(t*B+b)*E + :] = emb[x[b,t], :]
__global__ void embed_kernel(const int* __restrict__ x,
                             const float* __restrict__ emb) {
  int row = blockIdx.x;        // t*B + b
  int t = row >> 6;
  int b = row & 63;
  int tok = x[b * T + t];
  const float4* src = reinterpret_cast<const float4*>(emb + (size_t)tok * E);
  float4* dst = reinterpret_cast<float4*>(g_xs + (size_t)row * E);
  dst[threadIdx.x] = src[threadIdx.x];   // 128 threads * float4 = 512 floats
}

// ---------------------------------------------------------------------------
// C[M, 2048] = A[M, K] @ W[2048, K]^T + (b1 + b2)   (both A and W are K-major)
// Classic 128x128 tile / BK=8 / 8x8 per-thread SGEMM with global prefetch.
template <int K>
__global__ __launch_bounds__(256)
void sgemm_bias_kernel(const float* __restrict__ A,
                       const float* __restrict__ W,
                       const float* __restrict__ b1,
                       const float* __restrict__ b2,
                       float* __restrict__ C) {
  __shared__ float As[8][132];
  __shared__ float Ws[8][132];
  const int bm = blockIdx.y << 7;
  const int bn = blockIdx.x << 7;
  const int tid = threadIdx.x;
  const int tm = (tid >> 4) << 3;
  const int tn = (tid & 15) << 3;
  const int lrow = tid >> 1;
  const int lc4 = (tid & 1) << 2;
  const float* Ap = A + (size_t)(bm + lrow) * K + lc4;
  const float* Wp = W + (size_t)(bn + lrow) * K + lc4;

  float acc[8][8];
#pragma unroll
  for (int i = 0; i < 8; i++)
#pragma unroll
    for (int j = 0; j < 8; j++) acc[i][j] = 0.f;

  float4 av = *reinterpret_cast<const float4*>(Ap);
  float4 wv = *reinterpret_cast<const float4*>(Wp);

  for (int k0 = 0; k0 < K; k0 += 8) {
    __syncthreads();
    As[lc4 + 0][lrow] = av.x; As[lc4 + 1][lrow] = av.y;
    As[lc4 + 2][lrow] = av.z; As[lc4 + 3][lrow] = av.w;
    Ws[lc4 + 0][lrow] = wv.x; Ws[lc4 + 1][lrow] = wv.y;
    Ws[lc4 + 2][lrow] = wv.z; Ws[lc4 + 3][lrow] = wv.w;
    __syncthreads();
    if (k0 + 8 < K) {   // prefetch next k-slab while computing this one
      av = *reinterpret_cast<const float4*>(Ap + k0 + 8);
      wv = *reinterpret_cast<const float4*>(Wp + k0 + 8);
    }
#pragma unroll
    for (int kk = 0; kk < 8; kk++) {
      float ra[8], rw[8];
      *reinterpret_cast<float4*>(&ra[0]) = *reinterpret_cast<const float4*>(&As[kk][tm]);
      *reinterpret_cast<float4*>(&ra[4]) = *reinterpret_cast<const float4*>(&As[kk][tm + 4]);
      *reinterpret_cast<float4*>(&rw[0]) = *reinterpret_cast<const float4*>(&Ws[kk][tn]);
      *reinterpret_cast<float4*>(&rw[4]) = *reinterpret_cast<const float4*>(&Ws[kk][tn + 4]);
#pragma unroll
      for (int i = 0; i < 8; i++)
#pragma unroll
        for (int j = 0; j < 8; j++) acc[i][j] = fmaf(ra[i], rw[j], acc[i][j]);
    }
  }

  float bb[8];
#pragma unroll
  for (int j = 0; j < 8; j++) {
    int col = bn + tn + j;
    bb[j] = b1[col] + b2[col];
  }
#pragma unroll
  for (int i = 0; i < 8; i++) {
    size_t crow = (size_t)(bm + tm + i) * G + (bn + tn);
    float4 v0 = make_float4(acc[i][0] + bb[0], acc[i][1] + bb[1],
                            acc[i][2] + bb[2], acc[i][3] + bb[3]);
    float4 v1 = make_float4(acc[i][4] + bb[4], acc[i][5] + bb[5],
                            acc[i][6] + bb[6], acc[i][7] + bb[7]);
    *reinterpret_cast<float4*>(&C[crow]) = v0;
    *reinterpret_cast<float4*>(&C[crow + 4]) = v1;
  }
}

// ---------------------------------------------------------------------------
// One LSTM timestep, both directions fused in one launch.
// gates[b, g*H+j] = pre[tt, b, g*H+j] + sum_k h_prev[b,k] * Whh[g*H+j, k]
// Each thread owns 4 batches x 1 hidden unit x all 4 gates -> does the
// full c/h update in-register. Grid: (H/16 j-tiles, B/16 b-tiles, 2 dirs).
__global__ __launch_bounds__(64)
void lstm_step_kernel(const float* __restrict__ pre_f,
                      const float* __restrict__ pre_b,
                      const float* __restrict__ Whh_f,
                      const float* __restrict__ Whh_b,
                      float* __restrict__ out,
                      int t, int parity) {
  const int dir = blockIdx.z;
  const int tt = dir ? (T - 1 - t) : t;
  const float* pre = dir ? pre_b : pre_f;
  const float* Whh = dir ? Whh_b : Whh_f;
  const float* hp = g_h[parity][dir];
  float* hn = g_h[parity ^ 1][dir];
  float* cc = g_c[dir];
  const int j0 = blockIdx.x << 4;
  const int b0 = blockIdx.y << 4;
  const int tid = threadIdx.x;
  const int jj = tid & 15;
  const int bq = tid >> 4;   // 0..3 -> 4 batches each

  __shared__ float h_s[16][66];   // [b][k], padded (conflict-free reads)
  __shared__ float w_s[64][66];   // [gate*16 + jj][k], padded

  float acc[4][4];
#pragma unroll
  for (int g = 0; g < 4; g++)
#pragma unroll
    for (int i = 0; i < 4; i++) acc[g][i] = 0.f;

  for (int k0 = 0; k0 < H; k0 += 64) {
#pragma unroll
    for (int l = tid; l < 256; l += 64) {   // h tile: 16 b x 64 k
      int r = l >> 4, f4 = (l & 15) << 2;
      float4 v = *reinterpret_cast<const float4*>(&hp[(b0 + r) * H + k0 + f4]);
      h_s[r][f4 + 0] = v.x; h_s[r][f4 + 1] = v.y;
      h_s[r][f4 + 2] = v.z; h_s[r][f4 + 3] = v.w;
    }
#pragma unroll
    for (int l = tid; l < 1024; l += 64) {  // W tile: 64 gate-rows x 64 k
      int r = l >> 4, f4 = (l & 15) << 2;
      int gidx = r >> 4, jr = r & 15;
      float4 v = *reinterpret_cast<const float4*>(
          &Whh[(size_t)(gidx * H + j0 + jr) * H + k0 + f4]);
      w_s[r][f4 + 0] = v.x; w_s[r][f4 + 1] = v.y;
      w_s[r][f4 + 2] = v.z; w_s[r][f4 + 3] = v.w;
    }
    __syncthreads();
#pragma unroll 8
    for (int k = 0; k < 64; k += 2) {
      float2 w0 = *reinterpret_cast<const float2*>(&w_s[jj][k]);
      float2 w1 = *reinterpret_cast<const float2*>(&w_s[16 + jj][k]);
      float2 w2 = *reinterpret_cast<const float2*>(&w_s[32 + jj][k]);
      float2 w3 = *reinterpret_cast<const float2*>(&w_s[48 + jj][k]);
#pragma unroll
      for (int i = 0; i < 4; i++) {
        float2 hv = *reinterpret_cast<const float2*>(&h_s[(bq << 2) + i][k]);
        acc[0][i] += w0.x * hv.x + w0.y * hv.y;
        acc[1][i] += w1.x * hv.x + w1.y * hv.y;
        acc[2][i] += w2.x * hv.x + w2.y * hv.y;
        acc[3][i] += w3.x * hv.x + w3.y * hv.y;
      }
    }
    __syncthreads();
  }

#pragma unroll
  for (int i = 0; i < 4; i++) {
    int b = b0 + (bq << 2) + i;
    int j = j0 + jj;
    size_t base = ((size_t)tt * B + b) * G + j;
    float gi = acc[0][i] + pre[base];
    float gf = acc[1][i] + pre[base + H];
    float gg = acc[2][i] + pre[base + 2 * H];
    float go = acc[3][i] + pre[base + 3 * H];
    float ig = 1.f / (1.f + __expf(-gi));
    float fg = 1.f / (1.f + __expf(-gf));
    float gt = tanhf(gg);
    float og = 1.f / (1.f + __expf(-go));
    int sidx = b * H + j;
    float cn = fg * cc[sidx] + ig * gt;
    cc[sidx] = cn;
    float hv = og * tanhf(cn);
    hn[sidx] = hv;
    out[((size_t)tt * B + b) * (2 * H) + dir * H + j] = hv;
  }
}

// ---------------------------------------------------------------------------
// logits[b, t, tag] = out2[t*B+b, :] . fcW[tag, :] + fcb[tag]
__global__ __launch_bounds__(256)
void fc_kernel(const float* __restrict__ inp,
               const float* __restrict__ Wt,
               const float* __restrict__ bias,
               float* __restrict__ out) {
  __shared__ float rs[8][1024];
  int r0 = blockIdx.x << 3;
#pragma unroll
  for (int l = threadIdx.x; l < 2048; l += 256) {
    int r = l >> 8, f4 = (l & 255) << 2;
    *reinterpret_cast<float4*>(&rs[r][f4]) =
        *reinterpret_cast<const float4*>(&inp[(size_t)(r0 + r) * 1024 + f4]);
  }
  __syncthreads();
  int r = threadIdx.x >> 5;
  int tg = threadIdx.x & 31;
  int tag2 = tg + 32;
  bool has2 = (tag2 < TAGS);
  float a0 = 0.f, a1 = 0.f;
  for (int k = 0; k < 1024; k += 4) {
    float4 xv = *reinterpret_cast<const float4*>(&rs[r][k]);
    float4 w0 = *reinterpret_cast<const float4*>(&Wt[(size_t)tg * 1024 + k]);
    a0 += xv.x * w0.x + xv.y * w0.y + xv.z * w0.z + xv.w * w0.w;
    if (has2) {
      float4 w1 = *reinterpret_cast<const float4*>(&Wt[(size_t)tag2 * 1024 + k]);
      a1 += xv.x * w1.x + xv.y * w1.y + xv.z * w1.z + xv.w * w1.w;
    }
  }
  int row = r0 + r;
  int tq = row >> 6, bb = row & 63;
  size_t obase = ((size_t)bb * T + tq) * TAGS;
  out[obase + tg] = a0 + bias[tg];
  if (has2) out[obase + tag2] = a1 + bias[tag2];
}

// ---------------------------------------------------------------------------
extern "C" void kernel_launch(void* const* d_in, const int* in_sizes, int n_in,
                              void* d_out, int out_size) {
  const int* x = (const int*)d_in[0];
  const float* emb = (const float*)d_in[2];
  const float* Wih_f1 = (const float*)d_in[3];
  const float* Whh_f1 = (const float*)d_in[4];
  const float* bih_f1 = (const float*)d_in[5];
  const float* bhh_f1 = (const float*)d_in[6];
  const float* Wih_b1 = (const float*)d_in[7];
  const float* Whh_b1 = (const float*)d_in[8];
  const float* bih_b1 = (const float*)d_in[9];
  const float* bhh_b1 = (const float*)d_in[10];
  const float* Wih_f2 = (const float*)d_in[11];
  const float* Whh_f2 = (const float*)d_in[12];
  const float* bih_f2 = (const float*)d_in[13];
  const float* bhh_f2 = (const float*)d_in[14];
  const float* Wih_b2 = (const float*)d_in[15];
  const float* Whh_b2 = (const float*)d_in[16];
  const float* bih_b2 = (const float*)d_in[17];
  const float* bhh_b2 = (const float*)d_in[18];
  const float* fcW = (const float*)d_in[19];
  const float* fcb = (const float*)d_in[20];
  float* out = (float*)d_out;

  float *xs, *pre_f, *pre_b, *out1, *out2;
  cudaGetSymbolAddress((void**)&xs, g_xs);
  cudaGetSymbolAddress((void**)&pre_f, g_pre_f);
  cudaGetSymbolAddress((void**)&pre_b, g_pre_b);
  cudaGetSymbolAddress((void**)&out1, g_out1);
  cudaGetSymbolAddress((void**)&out2, g_out2);

  embed_kernel<<<M, 128>>>(x, emb);

  dim3 gg(G / 128, M / 128);      // (16, 128)
  dim3 sg(H / 16, B / 16, 2);     // (32, 4, 2) = 256 blocks/step

  // Layer 1
  zero_states_kernel<<<(B * H + 255) / 256, 256>>>();
  sgemm_bias_kernel<E><<<gg, 256>>>(xs, Wih_f1, bih_f1, bhh_f1, pre_f);
  sgemm_bias_kernel<E><<<gg, 256>>>(xs, Wih_b1, bih_b1, bhh_b1, pre_b);
  for (int t = 0; t < T; t++)
    lstm_step_kernel<<<sg, 64>>>(pre_f, pre_b, Whh_f1, Whh_b1, out1, t, t & 1);

  // Layer 2
  zero_states_kernel<<<(B * H + 255) / 256, 256>>>();
  sgemm_bias_kernel<2 * H><<<gg, 256>>>(out1, Wih_f2, bih_f2, bhh_f2, pre_f);
  sgemm_bias_kernel<2 * H><<<gg, 256>>>(out1, Wih_b2, bih_b2, bhh_b2, pre_b);
  for (int t = 0; t < T; t++)
    lstm_step_kernel<<<sg, 64>>>(pre_f, pre_b, Whh_f2, Whh_b2, out2, t, t & 1);

  fc_kernel<<<M / 8, 256>>>(out2, fcW, fcb, out);
}